// round 1
// baseline (speedup 1.0000x reference)
#include <cuda_runtime.h>
#include <math.h>

// Problem constants (fixed by the reference)
#define B_SZ   2
#define S_LEN  2048
#define NH     32
#define HD     128
#define H_DIM  4096
#define N_QKV  12288
#define M_ROWS (B_SZ * S_LEN)   // 4096

// ---------------------------------------------------------------------------
// Scratch (device globals: allocation-free contract)
// ---------------------------------------------------------------------------
__device__ float g_q[(size_t)B_SZ * NH * S_LEN * HD];   // [b,h,s,d]
__device__ float g_k[(size_t)B_SZ * NH * S_LEN * HD];
__device__ float g_v[(size_t)B_SZ * NH * S_LEN * HD];
__device__ float g_ctx[(size_t)M_ROWS * H_DIM];         // [b*s, h*d]

// ---------------------------------------------------------------------------
// SGEMM: C[M,N] = A[M,K] @ B[K,N], 128x128 block, BK=8, 8x8 per thread,
// double buffered. MODE 0: scatter into g_q/g_k/g_v. MODE 1: row-major C.
// ---------------------------------------------------------------------------
template <int MODE>
__global__ __launch_bounds__(256, 1)
void sgemm128(const float* __restrict__ A, const float* __restrict__ Bm,
              float* __restrict__ C, int K, int N)
{
    __shared__ float As[2][8][128];
    __shared__ float Bs[2][8][128];

    const int tid  = threadIdx.x;
    const int brow = blockIdx.y;
    const int bcol = blockIdx.x;

    const float* Ab = A  + (size_t)brow * 128 * K;
    const float* Bb = Bm + (size_t)bcol * 128;

    const int arow   = tid >> 1;          // 0..127
    const int acol   = (tid & 1) * 4;     // 0 or 4
    const int brow_l = tid >> 5;          // 0..7
    const int bcol_l = (tid & 31) * 4;    // 0..124

    // preload tile 0
    float4 aReg = *(const float4*)(Ab + (size_t)arow * K + acol);
    float4 bReg = *(const float4*)(Bb + (size_t)brow_l * N + bcol_l);
    As[0][acol + 0][arow] = aReg.x;
    As[0][acol + 1][arow] = aReg.y;
    As[0][acol + 2][arow] = aReg.z;
    As[0][acol + 3][arow] = aReg.w;
    *(float4*)&Bs[0][brow_l][bcol_l] = bReg;
    __syncthreads();

    const int ty = tid >> 4;   // 0..15
    const int tx = tid & 15;   // 0..15

    float acc[8][8];
#pragma unroll
    for (int i = 0; i < 8; ++i)
#pragma unroll
        for (int j = 0; j < 8; ++j) acc[i][j] = 0.f;

    const int ntiles = K / 8;
    int buf = 0;
    for (int t = 0; t < ntiles; ++t) {
        if (t + 1 < ntiles) {
            const int k0 = (t + 1) * 8;
            aReg = *(const float4*)(Ab + (size_t)arow * K + k0 + acol);
            bReg = *(const float4*)(Bb + (size_t)(k0 + brow_l) * N + bcol_l);
        }
#pragma unroll
        for (int kk = 0; kk < 8; ++kk) {
            float4 a0 = *(const float4*)&As[buf][kk][ty * 4];
            float4 a1 = *(const float4*)&As[buf][kk][64 + ty * 4];
            float4 b0 = *(const float4*)&Bs[buf][kk][tx * 4];
            float4 b1 = *(const float4*)&Bs[buf][kk][64 + tx * 4];
            float av[8] = {a0.x, a0.y, a0.z, a0.w, a1.x, a1.y, a1.z, a1.w};
            float bv[8] = {b0.x, b0.y, b0.z, b0.w, b1.x, b1.y, b1.z, b1.w};
#pragma unroll
            for (int i = 0; i < 8; ++i)
#pragma unroll
                for (int j = 0; j < 8; ++j)
                    acc[i][j] = fmaf(av[i], bv[j], acc[i][j]);
        }
        if (t + 1 < ntiles) {
            buf ^= 1;
            As[buf][acol + 0][arow] = aReg.x;
            As[buf][acol + 1][arow] = aReg.y;
            As[buf][acol + 2][arow] = aReg.z;
            As[buf][acol + 3][arow] = aReg.w;
            *(float4*)&Bs[buf][brow_l][bcol_l] = bReg;
            __syncthreads();
        }
    }

    int rows[8], cols[8];
#pragma unroll
    for (int i = 0; i < 4; ++i) {
        rows[i]     = ty * 4 + i;
        rows[i + 4] = 64 + ty * 4 + i;
        cols[i]     = tx * 4 + i;
        cols[i + 4] = 64 + tx * 4 + i;
    }

#pragma unroll
    for (int i = 0; i < 8; ++i) {
#pragma unroll
        for (int j = 0; j < 8; ++j) {
            const int m = brow * 128 + rows[i];
            const int n = bcol * 128 + cols[j];
            if (MODE == 0) {
                // scatter qkv -> [b,h,s,d]
                const int b_ = m >> 11;          // /2048
                const int s_ = m & 2047;
                const int which = n >> 12;       // /4096
                const int r  = n & 4095;
                const int h  = r >> 7;
                const int d  = r & 127;
                float* dst = (which == 0) ? g_q : (which == 1) ? g_k : g_v;
                dst[(((size_t)b_ * NH + h) * S_LEN + s_) * HD + d] = acc[i][j];
            } else {
                C[(size_t)m * N + n] = acc[i][j];
            }
        }
    }
}

// ---------------------------------------------------------------------------
// RoPE (in-place on g_q, g_k). Also folds 1/sqrt(HD) into q.
// ---------------------------------------------------------------------------
__global__ void rope_kernel()
{
    const int idx = blockIdx.x * blockDim.x + threadIdx.x; // B*NH*S*64 threads
    const int d  = idx & 63;
    const int s  = (idx >> 6) & (S_LEN - 1);
    const int bh = idx >> 17;                 // / (64*2048)

    // high-precision angle, reduced, then fp32 trig
    const double invf = exp(-9.210340371976184 * ((double)d / 64.0)); // ln(1e4)
    double ang = (double)s * invf;
    ang = remainder(ang, 6.283185307179586476925286766559);
    float c, sn;
    sincosf((float)ang, &sn, &c);

    const size_t base = ((size_t)bh * S_LEN + s) * HD;
    const float scale = 0.08838834764831845f; // 1/sqrt(128)

    const float q0 = g_q[base + d], q1 = g_q[base + d + 64];
    g_q[base + d]      = (q0 * c - q1 * sn) * scale;
    g_q[base + d + 64] = (q1 * c + q0 * sn) * scale;

    const float k0 = g_k[base + d], k1 = g_k[base + d + 64];
    g_k[base + d]      = k0 * c - k1 * sn;
    g_k[base + d + 64] = k1 * c + k0 * sn;
}

// ---------------------------------------------------------------------------
// Flash attention (fp32, causal). 64q x 64k tiles, HD=128.
// 256 threads: score stage 16x16 threads x (4q x 4k); PV stage (4q x 8d).
// ---------------------------------------------------------------------------
#define QK_PAD 68
#define ATTN_SMEM_FLOATS (128 * QK_PAD * 2 + 64 * 128 + 64 * 64)
#define ATTN_SMEM_BYTES  (ATTN_SMEM_FLOATS * 4)

__global__ __launch_bounds__(256, 1)
void flash_attn()
{
    extern __shared__ float sm[];
    float* Qt = sm;                       // [128][QK_PAD] (d-major, transposed)
    float* Kt = Qt + 128 * QK_PAD;        // [128][QK_PAD]
    float* Vs = Kt + 128 * QK_PAD;        // [64][128]
    float* Ps = Vs + 64 * 128;            // [64][64]

    const int qt = blockIdx.x;            // q tile (0..31)
    const int h  = blockIdx.y;
    const int b  = blockIdx.z;
    const int bh = b * NH + h;
    const int tid = threadIdx.x;
    const int ty = tid >> 4, tx = tid & 15;

    const float* Qg  = g_q + ((size_t)bh * S_LEN + (size_t)qt * 64) * HD;
    const float* Kg0 = g_k + (size_t)bh * S_LEN * HD;
    const float* Vg0 = g_v + (size_t)bh * S_LEN * HD;

    // load Q tile transposed (scaling already folded in by rope kernel)
    for (int e = tid; e < 64 * 128; e += 256) {
        const int q = e >> 7, d = e & 127;
        Qt[d * QK_PAD + q] = Qg[e];
    }

    float m_i[4], l_i[4];
    float O[4][8];
#pragma unroll
    for (int i = 0; i < 4; ++i) {
        m_i[i] = -1e30f; l_i[i] = 0.f;
#pragma unroll
        for (int j = 0; j < 8; ++j) O[i][j] = 0.f;
    }
    __syncthreads();

    for (int kt = 0; kt <= qt; ++kt) {
        const float* Kg = Kg0 + (size_t)kt * 64 * HD;
        const float* Vg = Vg0 + (size_t)kt * 64 * HD;
        for (int e = tid; e < 64 * 128; e += 256) {
            const int k = e >> 7, d = e & 127;
            Kt[d * QK_PAD + k] = Kg[e];
            Vs[e] = Vg[e];
        }
        __syncthreads();

        // scores: s[i][j] = sum_d Qt[d][ty*4+i] * Kt[d][tx*4+j]
        float s[4][4];
#pragma unroll
        for (int i = 0; i < 4; ++i)
#pragma unroll
            for (int j = 0; j < 4; ++j) s[i][j] = 0.f;

        for (int d = 0; d < 128; ++d) {
            float4 a = *(const float4*)&Qt[d * QK_PAD + ty * 4];
            float4 bk = *(const float4*)&Kt[d * QK_PAD + tx * 4];
            float av[4] = {a.x, a.y, a.z, a.w};
            float bv[4] = {bk.x, bk.y, bk.z, bk.w};
#pragma unroll
            for (int i = 0; i < 4; ++i)
#pragma unroll
                for (int j = 0; j < 4; ++j)
                    s[i][j] = fmaf(av[i], bv[j], s[i][j]);
        }

        if (kt == qt) {
            // diagonal tile: causal mask within tile
#pragma unroll
            for (int i = 0; i < 4; ++i)
#pragma unroll
                for (int j = 0; j < 4; ++j)
                    if ((tx * 4 + j) > (ty * 4 + i)) s[i][j] = -1e30f;
        }

        // online softmax per q row (reduce across 16 tx lanes via shfl)
        float alpha[4];
#pragma unroll
        for (int i = 0; i < 4; ++i) {
            float mx = fmaxf(fmaxf(s[i][0], s[i][1]), fmaxf(s[i][2], s[i][3]));
#pragma unroll
            for (int o = 8; o >= 1; o >>= 1)
                mx = fmaxf(mx, __shfl_xor_sync(0xffffffffu, mx, o));
            const float mnew = fmaxf(m_i[i], mx);
            alpha[i] = __expf(m_i[i] - mnew);
            float ps = 0.f;
#pragma unroll
            for (int j = 0; j < 4; ++j) {
                const float p = __expf(s[i][j] - mnew);
                s[i][j] = p;
                ps += p;
            }
#pragma unroll
            for (int o = 8; o >= 1; o >>= 1)
                ps += __shfl_xor_sync(0xffffffffu, ps, o);
            l_i[i] = l_i[i] * alpha[i] + ps;
            m_i[i] = mnew;
#pragma unroll
            for (int j = 0; j < 8; ++j) O[i][j] *= alpha[i];
            // stash probabilities
#pragma unroll
            for (int j = 0; j < 4; ++j)
                Ps[(ty * 4 + i) * 64 + tx * 4 + j] = s[i][j];
        }
        __syncthreads();

        // O += P @ V   (thread: 4 q-rows x 8 d-cols at tx*8)
        for (int k = 0; k < 64; ++k) {
            float4 v0 = *(const float4*)&Vs[k * 128 + tx * 8];
            float4 v1 = *(const float4*)&Vs[k * 128 + tx * 8 + 4];
            const float vv[8] = {v0.x, v0.y, v0.z, v0.w, v1.x, v1.y, v1.z, v1.w};
#pragma unroll
            for (int i = 0; i < 4; ++i) {
                const float p = Ps[(ty * 4 + i) * 64 + k];
#pragma unroll
                for (int j = 0; j < 8; ++j)
                    O[i][j] = fmaf(p, vv[j], O[i][j]);
            }
        }
        __syncthreads();
    }

    // write ctx: [b*S + q][h*128 + d]
#pragma unroll
    for (int i = 0; i < 4; ++i) {
        const float inv = 1.f / l_i[i];
        const int qg = qt * 64 + ty * 4 + i;
        float* dst = g_ctx + ((size_t)b * S_LEN + qg) * H_DIM + h * HD + tx * 8;
#pragma unroll
        for (int j = 0; j < 8; ++j) dst[j] = O[i][j] * inv;
    }
}

// ---------------------------------------------------------------------------
// launch
// ---------------------------------------------------------------------------
extern "C" void kernel_launch(void* const* d_in, const int* in_sizes, int n_in,
                              void* d_out, int out_size)
{
    const float* x    = (const float*)d_in[0];
    const float* Wqkv = (const float*)d_in[1];
    const float* Wo   = (const float*)d_in[2];
    float* out = (float*)d_out;

    float* ctx = nullptr;
    cudaGetSymbolAddress((void**)&ctx, g_ctx);

    // 1) QKV projection, scattered to [b,h,s,d]
    dim3 g1(N_QKV / 128, M_ROWS / 128);   // (96, 32)
    sgemm128<0><<<g1, 256>>>(x, Wqkv, nullptr, H_DIM, N_QKV);

    // 2) RoPE + q-scaling
    const int rope_threads = B_SZ * NH * S_LEN * 64;
    rope_kernel<<<rope_threads / 256, 256>>>();

    // 3) flash attention
    cudaFuncSetAttribute(flash_attn, cudaFuncAttributeMaxDynamicSharedMemorySize,
                         ATTN_SMEM_BYTES);
    dim3 ga(S_LEN / 64, NH, B_SZ);        // (32, 32, 2)
    flash_attn<<<ga, 256, ATTN_SMEM_BYTES>>>();

    // 4) output projection -> d_out
    dim3 g2(H_DIM / 128, M_ROWS / 128);   // (32, 32)
    sgemm128<1><<<g2, 256>>>(ctx, Wo, out, H_DIM, H_DIM);
}

// round 3
// speedup vs baseline: 1.3343x; 1.3343x over previous
#include <cuda_runtime.h>
#include <cuda_bf16.h>
#include <math.h>
#include <stdint.h>

// Problem constants
#define B_SZ   2
#define S_LEN  2048
#define NH     32
#define HD     128
#define H_DIM  4096
#define N_QKV  12288
#define M_ROWS (B_SZ * S_LEN)   // 4096

// ---------------------------------------------------------------------------
// Scratch (device globals: allocation-free contract)
// ---------------------------------------------------------------------------
__device__ float g_q[(size_t)B_SZ * NH * S_LEN * HD];
__device__ float g_k[(size_t)B_SZ * NH * S_LEN * HD];
__device__ float g_v[(size_t)B_SZ * NH * S_LEN * HD];
__device__ float g_ctx[(size_t)M_ROWS * H_DIM];

// bf16 split operands
__device__ __nv_bfloat16 g_xh[(size_t)M_ROWS * H_DIM];
__device__ __nv_bfloat16 g_xl[(size_t)M_ROWS * H_DIM];
__device__ __nv_bfloat16 g_wqkv_h[(size_t)N_QKV * H_DIM];   // transposed [N,K]
__device__ __nv_bfloat16 g_wqkv_l[(size_t)N_QKV * H_DIM];
__device__ __nv_bfloat16 g_wo_h[(size_t)H_DIM * H_DIM];     // transposed [N,K]
__device__ __nv_bfloat16 g_wo_l[(size_t)H_DIM * H_DIM];
__device__ __nv_bfloat16 g_ch[(size_t)M_ROWS * H_DIM];
__device__ __nv_bfloat16 g_cl[(size_t)M_ROWS * H_DIM];

// ---------------------------------------------------------------------------
// Helpers (baseline PTX only: sm_80-era features, valid on plain sm_103)
// ---------------------------------------------------------------------------
__device__ __forceinline__ uint32_t smem_u32(const void* p) {
    uint32_t a;
    asm("{ .reg .u64 t; cvta.to.shared.u64 t, %1; cvt.u32.u64 %0, t; }"
        : "=r"(a) : "l"(p));
    return a;
}

#define SW64(o) ((o) ^ (((o) >> 3) & 0x30))

#define CP_ASYNC16(dst, src) \
    asm volatile("cp.async.cg.shared.global [%0], [%1], 16;" \
                 :: "r"(dst), "l"(src))
#define CP_COMMIT() asm volatile("cp.async.commit_group;" ::: "memory")

#define LDSM_X4(r0, r1, r2, r3, a) \
    asm volatile("ldmatrix.sync.aligned.m8n8.x4.shared.b16 {%0,%1,%2,%3}, [%4];" \
                 : "=r"(r0), "=r"(r1), "=r"(r2), "=r"(r3) : "r"(a))

#define MMA_BF16(d, a, b0_, b1_)                                               \
    asm volatile("mma.sync.aligned.m16n8k16.row.col.f32.bf16.bf16.f32 "        \
                 "{%0,%1,%2,%3}, {%4,%5,%6,%7}, {%8,%9}, {%0,%1,%2,%3};"       \
                 : "+f"((d)[0]), "+f"((d)[1]), "+f"((d)[2]), "+f"((d)[3])      \
                 : "r"((a)[0]), "r"((a)[1]), "r"((a)[2]), "r"((a)[3]),         \
                   "r"(b0_), "r"(b1_))

// ---------------------------------------------------------------------------
// Conversion kernels
// ---------------------------------------------------------------------------
__global__ void split_kernel(const float* __restrict__ X,
                             __nv_bfloat16* __restrict__ Xh,
                             __nv_bfloat16* __restrict__ Xl, int n4)
{
    int i = blockIdx.x * blockDim.x + threadIdx.x;
    if (i >= n4) return;
    float4 v = ((const float4*)X)[i];
    __nv_bfloat16 h0 = __float2bfloat16(v.x), h1 = __float2bfloat16(v.y);
    __nv_bfloat16 h2 = __float2bfloat16(v.z), h3 = __float2bfloat16(v.w);
    __nv_bfloat162* H = (__nv_bfloat162*)Xh;
    __nv_bfloat162* L = (__nv_bfloat162*)Xl;
    H[2*i]   = __nv_bfloat162(h0, h1);
    H[2*i+1] = __nv_bfloat162(h2, h3);
    L[2*i]   = __nv_bfloat162(__float2bfloat16(v.x - __bfloat162float(h0)),
                              __float2bfloat16(v.y - __bfloat162float(h1)));
    L[2*i+1] = __nv_bfloat162(__float2bfloat16(v.z - __bfloat162float(h2)),
                              __float2bfloat16(v.w - __bfloat162float(h3)));
}

// W [K,N] fp32 row-major -> Th/Tl [N,K] bf16 row-major
__global__ void transpose_split(const float* __restrict__ W,
                                __nv_bfloat16* __restrict__ Th,
                                __nv_bfloat16* __restrict__ Tl, int K, int N)
{
    __shared__ float t[32][33];
    const int n0 = blockIdx.x * 32, k0 = blockIdx.y * 32;
    const int tx = threadIdx.x, ty0 = threadIdx.y;
#pragma unroll
    for (int i = 0; i < 4; ++i) {
        int ty = ty0 * 4 + i;
        t[ty][tx] = W[(size_t)(k0 + ty) * N + n0 + tx];
    }
    __syncthreads();
#pragma unroll
    for (int i = 0; i < 4; ++i) {
        int ty = ty0 * 4 + i;
        float v = t[tx][ty];
        __nv_bfloat16 h = __float2bfloat16(v);
        size_t o = (size_t)(n0 + ty) * K + k0 + tx;
        Th[o] = h;
        Tl[o] = __float2bfloat16(v - __bfloat162float(h));
    }
}

// ---------------------------------------------------------------------------
// bf16 mma.sync GEMM: C[M,N] = (Ah+Al)[M,K] @ (Bh+Bl)[N,K]^T  (3-term split)
// 128x128 block tile, BK=32, cp.async double buffer, 8 warps (4x2),
// warp tile 32x64, m16n8k16 fragments via ldmatrix, SW64 smem swizzle.
// MODE 0: scatter into g_q/g_k/g_v.  MODE 1: row-major C.
// ---------------------------------------------------------------------------
#define BUF_STRIDE 32768
#define OFF_AH(b) ((b) * BUF_STRIDE + 0)
#define OFF_AL(b) ((b) * BUF_STRIDE + 8192)
#define OFF_BH(b) ((b) * BUF_STRIDE + 16384)
#define OFF_BL(b) ((b) * BUF_STRIDE + 24576)
#define GEMM_SMEM (2 * BUF_STRIDE)

template <int MODE>
__global__ __launch_bounds__(256, 2)
void gemm_bf16(const __nv_bfloat16* __restrict__ Ah, const __nv_bfloat16* __restrict__ Al,
               const __nv_bfloat16* __restrict__ Bh, const __nv_bfloat16* __restrict__ Bl,
               float* __restrict__ C, int K, int N)
{
    extern __shared__ char sm[];
    const uint32_t sb = smem_u32(sm);
    const int tid = threadIdx.x;
    const int wid = tid >> 5, lane = tid & 31;
    const int wm = wid >> 1, wn = wid & 1;          // 4 x 2 warp grid
    const int m0 = blockIdx.x * 128;
    const int n0 = blockIdx.y * 128;
    const size_t Kb = (size_t)K * 2;                // row bytes

    const char* pAh = (const char*)Ah;
    const char* pAl = (const char*)Al;
    const char* pBh = (const char*)Bh;
    const char* pBl = (const char*)Bl;

    // per-thread load coords: 2 chunks per stream per tile
    const int r0c  = (tid >> 2) * 2;       // rows: tid/4 -> handles 2 rows? no:
    // chunk id = i*256 + tid ; r = id>>2 ; c16 = (id&3)*16
    float acc[2][8][4];
#pragma unroll
    for (int a = 0; a < 2; ++a)
#pragma unroll
        for (int b = 0; b < 8; ++b)
#pragma unroll
            for (int c = 0; c < 4; ++c) acc[a][b][c] = 0.f;
    (void)r0c;

    const int ntiles = K / 32;

    // ---- tile loader ----
    auto load_tile = [&](int t, int buf) {
        const size_t kb = (size_t)t * 64;   // 32 bf16 = 64 bytes
#pragma unroll
        for (int i = 0; i < 2; ++i) {
            const int id  = i * 256 + tid;
            const int r   = id >> 2;
            const int c16 = (id & 3) * 16;
            const uint32_t so = SW64(r * 64 + c16);
            const size_t ga = (size_t)(m0 + r) * Kb + kb + c16;
            const size_t gb = (size_t)(n0 + r) * Kb + kb + c16;
            CP_ASYNC16(sb + OFF_AH(buf) + so, pAh + ga);
            CP_ASYNC16(sb + OFF_AL(buf) + so, pAl + ga);
            CP_ASYNC16(sb + OFF_BH(buf) + so, pBh + gb);
            CP_ASYNC16(sb + OFF_BL(buf) + so, pBl + gb);
        }
        CP_COMMIT();
    };

    load_tile(0, 0);

    const int rowA = lane & 15;
    const int kA   = (lane >> 4) << 4;            // 0 or 16 bytes
    const int nIn  = (lane & 7) + ((lane >> 4) << 3);
    const int kB   = ((lane >> 3) & 1) * 16;      // 0 or 16 bytes

    for (int t = 0; t < ntiles; ++t) {
        const int buf = t & 1;
        if (t + 1 < ntiles) {
            load_tile(t + 1, buf ^ 1);
            asm volatile("cp.async.wait_group 1;" ::: "memory");
        } else {
            asm volatile("cp.async.wait_group 0;" ::: "memory");
        }
        __syncthreads();

        const uint32_t bAh = sb + OFF_AH(buf);
        const uint32_t bAl = sb + OFF_AL(buf);
        const uint32_t bBh = sb + OFF_BH(buf);
        const uint32_t bBl = sb + OFF_BL(buf);

#pragma unroll
        for (int ks = 0; ks < 2; ++ks) {
            const int kso = ks * 32;
            uint32_t ah[2][4], al[2][4];
#pragma unroll
            for (int mi = 0; mi < 2; ++mi) {
                const uint32_t off = SW64((wm * 32 + mi * 16 + rowA) * 64 + kA + kso);
                LDSM_X4(ah[mi][0], ah[mi][1], ah[mi][2], ah[mi][3], bAh + off);
                LDSM_X4(al[mi][0], al[mi][1], al[mi][2], al[mi][3], bAl + off);
            }
#pragma unroll
            for (int np = 0; np < 4; ++np) {
                const uint32_t off = SW64((wn * 64 + np * 16 + nIn) * 64 + kB + kso);
                uint32_t h0, h1, h2, h3, l0, l1, l2, l3;
                LDSM_X4(h0, h1, h2, h3, bBh + off);
                LDSM_X4(l0, l1, l2, l3, bBl + off);
#pragma unroll
                for (int mi = 0; mi < 2; ++mi) {
                    MMA_BF16(acc[mi][np * 2],     ah[mi], h0, h1);
                    MMA_BF16(acc[mi][np * 2],     al[mi], h0, h1);
                    MMA_BF16(acc[mi][np * 2],     ah[mi], l0, l1);
                    MMA_BF16(acc[mi][np * 2 + 1], ah[mi], h2, h3);
                    MMA_BF16(acc[mi][np * 2 + 1], al[mi], h2, h3);
                    MMA_BF16(acc[mi][np * 2 + 1], ah[mi], l2, l3);
                }
            }
        }
        __syncthreads();
    }

    // ---- epilogue ----
    const int rbase = m0 + wm * 32 + (lane >> 2);
    const int cbase = n0 + wn * 64 + (lane & 3) * 2;
#pragma unroll
    for (int mi = 0; mi < 2; ++mi) {
#pragma unroll
        for (int ni = 0; ni < 8; ++ni) {
            const int c = cbase + ni * 8;
#pragma unroll
            for (int hh = 0; hh < 2; ++hh) {
                const int r = rbase + mi * 16 + hh * 8;
                float2 v = make_float2(acc[mi][ni][hh * 2], acc[mi][ni][hh * 2 + 1]);
                if (MODE == 1) {
                    *(float2*)(C + (size_t)r * N + c) = v;
                } else {
                    const int which = c >> 12;
                    const int rr = c & 4095;
                    const int h = rr >> 7, d0 = rr & 127;
                    const int b_ = r >> 11, s_ = r & 2047;
                    float* base = (which == 0) ? g_q : (which == 1) ? g_k : g_v;
                    *(float2*)(base + (((size_t)b_ * NH + h) * S_LEN + s_) * HD + d0) = v;
                }
            }
        }
    }
}

// ---------------------------------------------------------------------------
// RoPE (in-place on g_q, g_k). Also folds 1/sqrt(HD) into q.
// ---------------------------------------------------------------------------
__global__ void rope_kernel()
{
    const int idx = blockIdx.x * blockDim.x + threadIdx.x;
    const int d  = idx & 63;
    const int s  = (idx >> 6) & (S_LEN - 1);
    const int bh = idx >> 17;

    const double invf = exp(-9.210340371976184 * ((double)d / 64.0));
    double ang = (double)s * invf;
    ang = remainder(ang, 6.283185307179586476925286766559);
    float c, sn;
    sincosf((float)ang, &sn, &c);

    const size_t base = ((size_t)bh * S_LEN + s) * HD;
    const float scale = 0.08838834764831845f;

    const float q0 = g_q[base + d], q1 = g_q[base + d + 64];
    g_q[base + d]      = (q0 * c - q1 * sn) * scale;
    g_q[base + d + 64] = (q1 * c + q0 * sn) * scale;

    const float k0 = g_k[base + d], k1 = g_k[base + d + 64];
    g_k[base + d]      = k0 * c - k1 * sn;
    g_k[base + d + 64] = k1 * c + k0 * sn;
}

// ---------------------------------------------------------------------------
// Flash attention (fp32, causal). 64q x 64k tiles, HD=128. (validated R1)
// ---------------------------------------------------------------------------
#define QK_PAD 68
#define ATTN_SMEM_FLOATS (128 * QK_PAD * 2 + 64 * 128 + 64 * 64)
#define ATTN_SMEM_BYTES  (ATTN_SMEM_FLOATS * 4)

__global__ __launch_bounds__(256, 1)
void flash_attn()
{
    extern __shared__ float smf[];
    float* Qt = smf;
    float* Kt = Qt + 128 * QK_PAD;
    float* Vs = Kt + 128 * QK_PAD;
    float* Ps = Vs + 64 * 128;

    const int qt = blockIdx.x;
    const int h  = blockIdx.y;
    const int b  = blockIdx.z;
    const int bh = b * NH + h;
    const int tid = threadIdx.x;
    const int ty = tid >> 4, tx = tid & 15;

    const float* Qg  = g_q + ((size_t)bh * S_LEN + (size_t)qt * 64) * HD;
    const float* Kg0 = g_k + (size_t)bh * S_LEN * HD;
    const float* Vg0 = g_v + (size_t)bh * S_LEN * HD;

    for (int e = tid; e < 64 * 128; e += 256) {
        const int q = e >> 7, d = e & 127;
        Qt[d * QK_PAD + q] = Qg[e];
    }

    float m_i[4], l_i[4];
    float O[4][8];
#pragma unroll
    for (int i = 0; i < 4; ++i) {
        m_i[i] = -1e30f; l_i[i] = 0.f;
#pragma unroll
        for (int j = 0; j < 8; ++j) O[i][j] = 0.f;
    }
    __syncthreads();

    for (int kt = 0; kt <= qt; ++kt) {
        const float* Kg = Kg0 + (size_t)kt * 64 * HD;
        const float* Vg = Vg0 + (size_t)kt * 64 * HD;
        for (int e = tid; e < 64 * 128; e += 256) {
            const int k = e >> 7, d = e & 127;
            Kt[d * QK_PAD + k] = Kg[e];
            Vs[e] = Vg[e];
        }
        __syncthreads();

        float s[4][4];
#pragma unroll
        for (int i = 0; i < 4; ++i)
#pragma unroll
            for (int j = 0; j < 4; ++j) s[i][j] = 0.f;

        for (int d = 0; d < 128; ++d) {
            float4 a = *(const float4*)&Qt[d * QK_PAD + ty * 4];
            float4 bk = *(const float4*)&Kt[d * QK_PAD + tx * 4];
            float av[4] = {a.x, a.y, a.z, a.w};
            float bv[4] = {bk.x, bk.y, bk.z, bk.w};
#pragma unroll
            for (int i = 0; i < 4; ++i)
#pragma unroll
                for (int j = 0; j < 4; ++j)
                    s[i][j] = fmaf(av[i], bv[j], s[i][j]);
        }

        if (kt == qt) {
#pragma unroll
            for (int i = 0; i < 4; ++i)
#pragma unroll
                for (int j = 0; j < 4; ++j)
                    if ((tx * 4 + j) > (ty * 4 + i)) s[i][j] = -1e30f;
        }

        float alpha[4];
#pragma unroll
        for (int i = 0; i < 4; ++i) {
            float mx = fmaxf(fmaxf(s[i][0], s[i][1]), fmaxf(s[i][2], s[i][3]));
#pragma unroll
            for (int o = 8; o >= 1; o >>= 1)
                mx = fmaxf(mx, __shfl_xor_sync(0xffffffffu, mx, o));
            const float mnew = fmaxf(m_i[i], mx);
            alpha[i] = __expf(m_i[i] - mnew);
            float ps = 0.f;
#pragma unroll
            for (int j = 0; j < 4; ++j) {
                const float p = __expf(s[i][j] - mnew);
                s[i][j] = p;
                ps += p;
            }
#pragma unroll
            for (int o = 8; o >= 1; o >>= 1)
                ps += __shfl_xor_sync(0xffffffffu, ps, o);
            l_i[i] = l_i[i] * alpha[i] + ps;
            m_i[i] = mnew;
#pragma unroll
            for (int j = 0; j < 8; ++j) O[i][j] *= alpha[i];
#pragma unroll
            for (int j = 0; j < 4; ++j)
                Ps[(ty * 4 + i) * 64 + tx * 4 + j] = s[i][j];
        }
        __syncthreads();

        for (int k = 0; k < 64; ++k) {
            float4 v0 = *(const float4*)&Vs[k * 128 + tx * 8];
            float4 v1 = *(const float4*)&Vs[k * 128 + tx * 8 + 4];
            const float vv[8] = {v0.x, v0.y, v0.z, v0.w, v1.x, v1.y, v1.z, v1.w};
#pragma unroll
            for (int i = 0; i < 4; ++i) {
                const float p = Ps[(ty * 4 + i) * 64 + k];
#pragma unroll
                for (int j = 0; j < 8; ++j)
                    O[i][j] = fmaf(p, vv[j], O[i][j]);
            }
        }
        __syncthreads();
    }

#pragma unroll
    for (int i = 0; i < 4; ++i) {
        const float inv = 1.f / l_i[i];
        const int qg = qt * 64 + ty * 4 + i;
        float* dst = g_ctx + ((size_t)b * S_LEN + qg) * H_DIM + h * HD + tx * 8;
#pragma unroll
        for (int j = 0; j < 8; ++j) dst[j] = O[i][j] * inv;
    }
}

// ---------------------------------------------------------------------------
// launch
// ---------------------------------------------------------------------------
extern "C" void kernel_launch(void* const* d_in, const int* in_sizes, int n_in,
                              void* d_out, int out_size)
{
    const float* x    = (const float*)d_in[0];
    const float* Wqkv = (const float*)d_in[1];
    const float* Wo   = (const float*)d_in[2];
    float* out = (float*)d_out;

    float* ctx = nullptr;  cudaGetSymbolAddress((void**)&ctx, g_ctx);
    __nv_bfloat16 *xh, *xl, *wqh, *wql, *woh, *wol, *ch, *cl;
    cudaGetSymbolAddress((void**)&xh,  g_xh);
    cudaGetSymbolAddress((void**)&xl,  g_xl);
    cudaGetSymbolAddress((void**)&wqh, g_wqkv_h);
    cudaGetSymbolAddress((void**)&wql, g_wqkv_l);
    cudaGetSymbolAddress((void**)&woh, g_wo_h);
    cudaGetSymbolAddress((void**)&wol, g_wo_l);
    cudaGetSymbolAddress((void**)&ch,  g_ch);
    cudaGetSymbolAddress((void**)&cl,  g_cl);

    static bool attr_done = false;
    if (!attr_done) {
        cudaFuncSetAttribute(gemm_bf16<0>, cudaFuncAttributeMaxDynamicSharedMemorySize, GEMM_SMEM);
        cudaFuncSetAttribute(gemm_bf16<1>, cudaFuncAttributeMaxDynamicSharedMemorySize, GEMM_SMEM);
        cudaFuncSetAttribute(flash_attn,   cudaFuncAttributeMaxDynamicSharedMemorySize, ATTN_SMEM_BYTES);
        attr_done = true;
    }

    // 0) split/transpose conversions
    {
        const int n4 = (M_ROWS * H_DIM) / 4;
        split_kernel<<<(n4 + 255) / 256, 256>>>(x, xh, xl, n4);
        transpose_split<<<dim3(N_QKV / 32, H_DIM / 32), dim3(32, 8)>>>(Wqkv, wqh, wql, H_DIM, N_QKV);
        transpose_split<<<dim3(H_DIM / 32, H_DIM / 32), dim3(32, 8)>>>(Wo, woh, wol, H_DIM, H_DIM);
    }

    // 1) QKV projection (mma.sync bf16 split), scatter into g_q/g_k/g_v
    gemm_bf16<0><<<dim3(M_ROWS / 128, N_QKV / 128), 256, GEMM_SMEM>>>(
        xh, xl, wqh, wql, nullptr, H_DIM, N_QKV);

    // 2) RoPE + q scaling
    const int rope_threads = B_SZ * NH * S_LEN * 64;
    rope_kernel<<<rope_threads / 256, 256>>>();

    // 3) flash attention (fp32)
    dim3 ga(S_LEN / 64, NH, B_SZ);
    flash_attn<<<ga, 256, ATTN_SMEM_BYTES>>>();

    // 4) split ctx, then output projection -> d_out
    {
        const int n4 = (M_ROWS * H_DIM) / 4;
        split_kernel<<<(n4 + 255) / 256, 256>>>(ctx, ch, cl, n4);
    }
    gemm_bf16<1><<<dim3(M_ROWS / 128, H_DIM / 128), 256, GEMM_SMEM>>>(
        ch, cl, woh, wol, out, H_DIM, H_DIM);
}

// round 4
// speedup vs baseline: 3.2160x; 2.4103x over previous
#include <cuda_runtime.h>
#include <cuda_bf16.h>
#include <math.h>
#include <stdint.h>

// Problem constants
#define B_SZ   2
#define S_LEN  2048
#define NH     32
#define HD     128
#define H_DIM  4096
#define N_QKV  12288
#define M_ROWS (B_SZ * S_LEN)   // 4096

// ---------------------------------------------------------------------------
// Scratch (device globals: allocation-free contract)
// ---------------------------------------------------------------------------
__device__ float g_q[(size_t)B_SZ * NH * S_LEN * HD];
__device__ float g_k[(size_t)B_SZ * NH * S_LEN * HD];
__device__ float g_v[(size_t)B_SZ * NH * S_LEN * HD];
__device__ float g_ctx[(size_t)M_ROWS * H_DIM];

// bf16 split operands for projections
__device__ __nv_bfloat16 g_xh[(size_t)M_ROWS * H_DIM];
__device__ __nv_bfloat16 g_xl[(size_t)M_ROWS * H_DIM];
__device__ __nv_bfloat16 g_wqkv_h[(size_t)N_QKV * H_DIM];
__device__ __nv_bfloat16 g_wqkv_l[(size_t)N_QKV * H_DIM];
__device__ __nv_bfloat16 g_wo_h[(size_t)H_DIM * H_DIM];
__device__ __nv_bfloat16 g_wo_l[(size_t)H_DIM * H_DIM];
__device__ __nv_bfloat16 g_ch[(size_t)M_ROWS * H_DIM];
__device__ __nv_bfloat16 g_cl[(size_t)M_ROWS * H_DIM];

// bf16 split operands for attention
__device__ __nv_bfloat16 g_qh[(size_t)B_SZ * NH * S_LEN * HD];  // [bh][s][d]
__device__ __nv_bfloat16 g_ql[(size_t)B_SZ * NH * S_LEN * HD];
__device__ __nv_bfloat16 g_kh[(size_t)B_SZ * NH * S_LEN * HD];
__device__ __nv_bfloat16 g_kl[(size_t)B_SZ * NH * S_LEN * HD];
__device__ __nv_bfloat16 g_vth[(size_t)B_SZ * NH * HD * S_LEN]; // [bh][d][s]
__device__ __nv_bfloat16 g_vtl[(size_t)B_SZ * NH * HD * S_LEN];

// ---------------------------------------------------------------------------
// Helpers (baseline PTX: sm_80-era, valid on plain sm_103)
// ---------------------------------------------------------------------------
__device__ __forceinline__ uint32_t smem_u32(const void* p) {
    uint32_t a;
    asm("{ .reg .u64 t; cvta.to.shared.u64 t, %1; cvt.u32.u64 %0, t; }"
        : "=r"(a) : "l"(p));
    return a;
}

#define SW64(o)  ((o) ^ (((o) >> 3) & 0x30))
#define SW128(o) ((o) ^ (((o) >> 3) & 0x70))

#define CP_ASYNC16(dst, src) \
    asm volatile("cp.async.cg.shared.global [%0], [%1], 16;" :: "r"(dst), "l"(src))
#define CP_COMMIT() asm volatile("cp.async.commit_group;" ::: "memory")

#define LDSM_X4(r0, r1, r2, r3, a) \
    asm volatile("ldmatrix.sync.aligned.m8n8.x4.shared.b16 {%0,%1,%2,%3}, [%4];" \
                 : "=r"(r0), "=r"(r1), "=r"(r2), "=r"(r3) : "r"(a))

#define MMA_BF16(d, a, b0_, b1_)                                               \
    asm volatile("mma.sync.aligned.m16n8k16.row.col.f32.bf16.bf16.f32 "        \
                 "{%0,%1,%2,%3}, {%4,%5,%6,%7}, {%8,%9}, {%0,%1,%2,%3};"       \
                 : "+f"((d)[0]), "+f"((d)[1]), "+f"((d)[2]), "+f"((d)[3])      \
                 : "r"((a)[0]), "r"((a)[1]), "r"((a)[2]), "r"((a)[3]),         \
                   "r"(b0_), "r"(b1_))

// pack two fp32 -> bf16x2 (x -> low half, y -> high half)
__device__ __forceinline__ uint32_t packbf2(float x, float y) {
    uint32_t r;
    asm("cvt.rn.bf16x2.f32 %0, %1, %2;" : "=r"(r) : "f"(y), "f"(x));
    return r;
}

// ---------------------------------------------------------------------------
// Conversion kernels
// ---------------------------------------------------------------------------
__global__ void split_kernel(const float* __restrict__ X,
                             __nv_bfloat16* __restrict__ Xh,
                             __nv_bfloat16* __restrict__ Xl, int n4)
{
    int i = blockIdx.x * blockDim.x + threadIdx.x;
    if (i >= n4) return;
    float4 v = ((const float4*)X)[i];
    __nv_bfloat16 h0 = __float2bfloat16(v.x), h1 = __float2bfloat16(v.y);
    __nv_bfloat16 h2 = __float2bfloat16(v.z), h3 = __float2bfloat16(v.w);
    __nv_bfloat162* H = (__nv_bfloat162*)Xh;
    __nv_bfloat162* L = (__nv_bfloat162*)Xl;
    H[2*i]   = __nv_bfloat162(h0, h1);
    H[2*i+1] = __nv_bfloat162(h2, h3);
    L[2*i]   = __nv_bfloat162(__float2bfloat16(v.x - __bfloat162float(h0)),
                              __float2bfloat16(v.y - __bfloat162float(h1)));
    L[2*i+1] = __nv_bfloat162(__float2bfloat16(v.z - __bfloat162float(h2)),
                              __float2bfloat16(v.w - __bfloat162float(h3)));
}

// W [K,N] fp32 row-major -> Th/Tl [N,K] bf16 row-major
__global__ void transpose_split(const float* __restrict__ W,
                                __nv_bfloat16* __restrict__ Th,
                                __nv_bfloat16* __restrict__ Tl, int K, int N)
{
    __shared__ float t[32][33];
    const int n0 = blockIdx.x * 32, k0 = blockIdx.y * 32;
    const int tx = threadIdx.x, ty0 = threadIdx.y;
#pragma unroll
    for (int i = 0; i < 4; ++i) {
        int ty = ty0 * 4 + i;
        t[ty][tx] = W[(size_t)(k0 + ty) * N + n0 + tx];
    }
    __syncthreads();
#pragma unroll
    for (int i = 0; i < 4; ++i) {
        int ty = ty0 * 4 + i;
        float v = t[tx][ty];
        __nv_bfloat16 h = __float2bfloat16(v);
        size_t o = (size_t)(n0 + ty) * K + k0 + tx;
        Th[o] = h;
        Tl[o] = __float2bfloat16(v - __bfloat162float(h));
    }
}

// ---------------------------------------------------------------------------
// bf16 mma.sync GEMM (validated R3). MODE0: scatter q/k/v. MODE1: row-major C.
// ---------------------------------------------------------------------------
#define BUF_STRIDE 32768
#define OFF_AH(b) ((b) * BUF_STRIDE + 0)
#define OFF_AL(b) ((b) * BUF_STRIDE + 8192)
#define OFF_BH(b) ((b) * BUF_STRIDE + 16384)
#define OFF_BL(b) ((b) * BUF_STRIDE + 24576)
#define GEMM_SMEM (2 * BUF_STRIDE)

template <int MODE>
__global__ __launch_bounds__(256, 2)
void gemm_bf16(const __nv_bfloat16* __restrict__ Ah, const __nv_bfloat16* __restrict__ Al,
               const __nv_bfloat16* __restrict__ Bh, const __nv_bfloat16* __restrict__ Bl,
               float* __restrict__ C, int K, int N)
{
    extern __shared__ char sm[];
    const uint32_t sb = smem_u32(sm);
    const int tid = threadIdx.x;
    const int wid = tid >> 5, lane = tid & 31;
    const int wm = wid >> 1, wn = wid & 1;
    const int m0 = blockIdx.x * 128;
    const int n0 = blockIdx.y * 128;
    const size_t Kb = (size_t)K * 2;

    const char* pAh = (const char*)Ah;
    const char* pAl = (const char*)Al;
    const char* pBh = (const char*)Bh;
    const char* pBl = (const char*)Bl;

    float acc[2][8][4];
#pragma unroll
    for (int a = 0; a < 2; ++a)
#pragma unroll
        for (int b = 0; b < 8; ++b)
#pragma unroll
            for (int c = 0; c < 4; ++c) acc[a][b][c] = 0.f;

    const int ntiles = K / 32;

    auto load_tile = [&](int t, int buf) {
        const size_t kb = (size_t)t * 64;
#pragma unroll
        for (int i = 0; i < 2; ++i) {
            const int id  = i * 256 + tid;
            const int r   = id >> 2;
            const int c16 = (id & 3) * 16;
            const uint32_t so = SW64(r * 64 + c16);
            const size_t ga = (size_t)(m0 + r) * Kb + kb + c16;
            const size_t gb = (size_t)(n0 + r) * Kb + kb + c16;
            CP_ASYNC16(sb + OFF_AH(buf) + so, pAh + ga);
            CP_ASYNC16(sb + OFF_AL(buf) + so, pAl + ga);
            CP_ASYNC16(sb + OFF_BH(buf) + so, pBh + gb);
            CP_ASYNC16(sb + OFF_BL(buf) + so, pBl + gb);
        }
        CP_COMMIT();
    };

    load_tile(0, 0);

    const int rowA = lane & 15;
    const int kA   = (lane >> 4) << 4;
    const int nIn  = (lane & 7) + ((lane >> 4) << 3);
    const int kB   = ((lane >> 3) & 1) * 16;

    for (int t = 0; t < ntiles; ++t) {
        const int buf = t & 1;
        if (t + 1 < ntiles) {
            load_tile(t + 1, buf ^ 1);
            asm volatile("cp.async.wait_group 1;" ::: "memory");
        } else {
            asm volatile("cp.async.wait_group 0;" ::: "memory");
        }
        __syncthreads();

        const uint32_t bAh = sb + OFF_AH(buf);
        const uint32_t bAl = sb + OFF_AL(buf);
        const uint32_t bBh = sb + OFF_BH(buf);
        const uint32_t bBl = sb + OFF_BL(buf);

#pragma unroll
        for (int ks = 0; ks < 2; ++ks) {
            const int kso = ks * 32;
            uint32_t ah[2][4], al[2][4];
#pragma unroll
            for (int mi = 0; mi < 2; ++mi) {
                const uint32_t off = SW64((wm * 32 + mi * 16 + rowA) * 64 + kA + kso);
                LDSM_X4(ah[mi][0], ah[mi][1], ah[mi][2], ah[mi][3], bAh + off);
                LDSM_X4(al[mi][0], al[mi][1], al[mi][2], al[mi][3], bAl + off);
            }
#pragma unroll
            for (int np = 0; np < 4; ++np) {
                const uint32_t off = SW64((wn * 64 + np * 16 + nIn) * 64 + kB + kso);
                uint32_t h0, h1, h2, h3, l0, l1, l2, l3;
                LDSM_X4(h0, h1, h2, h3, bBh + off);
                LDSM_X4(l0, l1, l2, l3, bBl + off);
#pragma unroll
                for (int mi = 0; mi < 2; ++mi) {
                    MMA_BF16(acc[mi][np * 2],     ah[mi], h0, h1);
                    MMA_BF16(acc[mi][np * 2],     al[mi], h0, h1);
                    MMA_BF16(acc[mi][np * 2],     ah[mi], l0, l1);
                    MMA_BF16(acc[mi][np * 2 + 1], ah[mi], h2, h3);
                    MMA_BF16(acc[mi][np * 2 + 1], al[mi], h2, h3);
                    MMA_BF16(acc[mi][np * 2 + 1], ah[mi], l2, l3);
                }
            }
        }
        __syncthreads();
    }

    const int rbase = m0 + wm * 32 + (lane >> 2);
    const int cbase = n0 + wn * 64 + (lane & 3) * 2;
#pragma unroll
    for (int mi = 0; mi < 2; ++mi) {
#pragma unroll
        for (int ni = 0; ni < 8; ++ni) {
            const int c = cbase + ni * 8;
#pragma unroll
            for (int hh = 0; hh < 2; ++hh) {
                const int r = rbase + mi * 16 + hh * 8;
                float2 v = make_float2(acc[mi][ni][hh * 2], acc[mi][ni][hh * 2 + 1]);
                if (MODE == 1) {
                    *(float2*)(C + (size_t)r * N + c) = v;
                } else {
                    const int which = c >> 12;
                    const int rr = c & 4095;
                    const int h = rr >> 7, d0 = rr & 127;
                    const int b_ = r >> 11, s_ = r & 2047;
                    float* base = (which == 0) ? g_q : (which == 1) ? g_k : g_v;
                    *(float2*)(base + (((size_t)b_ * NH + h) * S_LEN + s_) * HD + d0) = v;
                }
            }
        }
    }
}

// ---------------------------------------------------------------------------
// RoPE + bf16 hi/lo conversion for Q,K (scale folded into Q).
// ---------------------------------------------------------------------------
__global__ void rope_cvt()
{
    const int idx = blockIdx.x * blockDim.x + threadIdx.x;
    const int d  = idx & 63;
    const int s  = (idx >> 6) & (S_LEN - 1);
    const int bh = idx >> 17;

    const double invf = exp(-9.210340371976184 * ((double)d / 64.0));
    double ang = (double)s * invf;
    ang = remainder(ang, 6.283185307179586476925286766559);
    float c, sn;
    sincosf((float)ang, &sn, &c);

    const size_t base = ((size_t)bh * S_LEN + s) * HD;
    const float scale = 0.08838834764831845f;

    const float q0 = g_q[base + d], q1 = g_q[base + d + 64];
    const float qr0 = (q0 * c - q1 * sn) * scale;
    const float qr1 = (q1 * c + q0 * sn) * scale;
    const float k0 = g_k[base + d], k1 = g_k[base + d + 64];
    const float kr0 = k0 * c - k1 * sn;
    const float kr1 = k1 * c + k0 * sn;

    __nv_bfloat16 h;
    h = __float2bfloat16(qr0); g_qh[base + d] = h;
    g_ql[base + d] = __float2bfloat16(qr0 - __bfloat162float(h));
    h = __float2bfloat16(qr1); g_qh[base + d + 64] = h;
    g_ql[base + d + 64] = __float2bfloat16(qr1 - __bfloat162float(h));
    h = __float2bfloat16(kr0); g_kh[base + d] = h;
    g_kl[base + d] = __float2bfloat16(kr0 - __bfloat162float(h));
    h = __float2bfloat16(kr1); g_kh[base + d + 64] = h;
    g_kl[base + d + 64] = __float2bfloat16(kr1 - __bfloat162float(h));
}

// V [bh][s][d] fp32 -> V^T [bh][d][s] bf16 hi/lo
__global__ void v_cvt_t()
{
    __shared__ float t[32][33];
    const int bh = blockIdx.z;
    const int s0 = blockIdx.x * 32, d0 = blockIdx.y * 32;
    const int tx = threadIdx.x, ty0 = threadIdx.y;
    const float* src = g_v + (size_t)bh * S_LEN * HD;
#pragma unroll
    for (int i = 0; i < 4; ++i) {
        const int ty = ty0 * 4 + i;
        t[ty][tx] = src[(size_t)(s0 + ty) * HD + d0 + tx];
    }
    __syncthreads();
#pragma unroll
    for (int i = 0; i < 4; ++i) {
        const int ty = ty0 * 4 + i;
        const float v = t[tx][ty];                     // (s0+tx, d0+ty)
        const size_t o = (size_t)bh * HD * S_LEN + (size_t)(d0 + ty) * S_LEN + s0 + tx;
        __nv_bfloat16 h = __float2bfloat16(v);
        g_vth[o] = h;
        g_vtl[o] = __float2bfloat16(v - __bfloat162float(h));
    }
}

// ---------------------------------------------------------------------------
// Tensor-core flash attention (bf16 3-term split, causal).
// 8 warps, q-tile 128 (m16/warp), k-chunk 64. Q resident in smem;
// K/V double-buffered cp.async. O in registers, online softmax.
// Smem map (bytes): QH 0, QL 32768, K(buf): 65536+buf*32768 (hi), +16384 (lo),
//                   V(buf): 131072+buf*32768 (hi), +16384 (lo). Total 196608.
// ---------------------------------------------------------------------------
#define ATT_SMEM 196608
#define QH_OFF   0
#define QL_OFF   32768
#define K_OFF    65536
#define V_OFF    131072

__global__ __launch_bounds__(256, 1)
void flash_attn_mma()
{
    extern __shared__ char sm[];
    const uint32_t sb = smem_u32(sm);
    const int tid = threadIdx.x, wid = tid >> 5, lane = tid & 31;
    const int qt = gridDim.x - 1 - blockIdx.x;          // heavy tiles first
    const int h = blockIdx.y, b = blockIdx.z;
    const int bh = b * NH + h;
    const int q0 = qt * 128;

    const size_t qbase  = ((size_t)bh * S_LEN + q0) * HD;   // elements
    const size_t kbase  = (size_t)bh * S_LEN * HD;
    const size_t vtbase = (size_t)bh * HD * S_LEN;

    // ---- Q load (once): 2 streams x 128 rows x 16 chunks ----
#pragma unroll
    for (int i = 0; i < 16; ++i) {
        const int id = i * 256 + tid;
        const int strm = id >> 11;
        const int rem = id & 2047;
        const int r = rem >> 4, c = rem & 15;
        const int plane = c >> 3, cb = (c & 7) * 16;
        const uint32_t dst = sb + strm * 32768 + plane * 16384 + SW128(r * 128 + cb);
        const char* src = (const char*)(strm ? g_ql : g_qh) + (qbase + (size_t)r * HD) * 2 + c * 16;
        CP_ASYNC16(dst, src);
    }

    auto load_kv = [&](int j, int buf) {
        const uint32_t kbb = sb + K_OFF + buf * 32768;
        const uint32_t vbb = sb + V_OFF + buf * 32768;
#pragma unroll
        for (int i = 0; i < 8; ++i) {               // K: 2 strm x 64 rows x 16 c
            const int id = i * 256 + tid;
            const int strm = id >> 10;
            const int rem = id & 1023;
            const int r = rem >> 4, c = rem & 15;
            const int plane = c >> 3, cb = (c & 7) * 16;
            const uint32_t dst = kbb + strm * 16384 + plane * 8192 + SW128(r * 128 + cb);
            const char* src = (const char*)(strm ? g_kl : g_kh)
                              + (kbase + (size_t)(j * 64 + r) * HD) * 2 + c * 16;
            CP_ASYNC16(dst, src);
        }
#pragma unroll
        for (int i = 0; i < 8; ++i) {               // V^T: 2 strm x 128 d-rows x 8 c
            const int id = i * 256 + tid;
            const int strm = id >> 10;
            const int rem = id & 1023;
            const int r = rem >> 3, c = rem & 7;
            const uint32_t dst = vbb + strm * 16384 + SW128(r * 128 + c * 16);
            const char* src = (const char*)(strm ? g_vtl : g_vth)
                              + (vtbase + (size_t)r * S_LEN + j * 64) * 2 + c * 16;
            CP_ASYNC16(dst, src);
        }
        CP_COMMIT();
    };

    const int nchunks = 2 * qt + 2;
    load_kv(0, 0);
    CP_COMMIT();   // close the Q+chunk0 group boundary cleanly (Q issued pre-commit above)

    const int wq = wid * 16;
    const int rowA = lane & 15, kA = (lane >> 4) * 16;
    const int nIn = (lane & 7) + ((lane >> 4) << 3), kB = ((lane >> 3) & 1) * 16;

    float m0 = -1e30f, m1 = -1e30f, l0 = 0.f, l1 = 0.f;
    float O[16][4];
#pragma unroll
    for (int t = 0; t < 16; ++t)
#pragma unroll
        for (int c = 0; c < 4; ++c) O[t][c] = 0.f;

    for (int j = 0; j < nchunks; ++j) {
        const int buf = j & 1;
        if (j + 1 < nchunks) {
            load_kv(j + 1, buf ^ 1);
            asm volatile("cp.async.wait_group 1;" ::: "memory");
        } else {
            asm volatile("cp.async.wait_group 0;" ::: "memory");
        }
        __syncthreads();

        if (j * 64 <= q0 + wq + 15) {   // warp has at least one unmasked row
            // ---- scores: S = Q K^T ----
            float S[8][4];
#pragma unroll
            for (int t = 0; t < 8; ++t)
#pragma unroll
                for (int c = 0; c < 4; ++c) S[t][c] = 0.f;

            const uint32_t kbb = sb + K_OFF + buf * 32768;
#pragma unroll
            for (int kk = 0; kk < 8; ++kk) {
                const uint32_t aoff = (kk >> 2) * 16384 + SW128((wq + rowA) * 128 + (kk & 3) * 32 + kA);
                uint32_t ah[4], al[4];
                LDSM_X4(ah[0], ah[1], ah[2], ah[3], sb + QH_OFF + aoff);
                LDSM_X4(al[0], al[1], al[2], al[3], sb + QL_OFF + aoff);
#pragma unroll
                for (int nt = 0; nt < 4; ++nt) {
                    const uint32_t boff = (kk >> 2) * 8192 +
                        SW128((nt * 16 + nIn) * 128 + (kk & 3) * 32 + kB);
                    uint32_t kh0, kh1, kh2, kh3, kl0, kl1, kl2, kl3;
                    LDSM_X4(kh0, kh1, kh2, kh3, kbb + boff);
                    LDSM_X4(kl0, kl1, kl2, kl3, kbb + 16384 + boff);
                    MMA_BF16(S[nt * 2],     ah, kh0, kh1);
                    MMA_BF16(S[nt * 2],     al, kh0, kh1);
                    MMA_BF16(S[nt * 2],     ah, kl0, kl1);
                    MMA_BF16(S[nt * 2 + 1], ah, kh2, kh3);
                    MMA_BF16(S[nt * 2 + 1], al, kh2, kh3);
                    MMA_BF16(S[nt * 2 + 1], ah, kl2, kl3);
                }
            }

            // ---- causal mask (diagonal chunks only) ----
            if (j * 64 + 63 > q0 + wq) {
                const int rg0 = q0 + wq + (lane >> 2);
#pragma unroll
                for (int t = 0; t < 8; ++t) {
                    const int cg = j * 64 + t * 8 + 2 * (lane & 3);
                    if (cg > rg0)     S[t][0] = -1e30f;
                    if (cg + 1 > rg0) S[t][1] = -1e30f;
                    if (cg > rg0 + 8)     S[t][2] = -1e30f;
                    if (cg + 1 > rg0 + 8) S[t][3] = -1e30f;
                }
            }

            // ---- online softmax (rows r and r+8 per thread) ----
            float mx0 = -1e30f, mx1 = -1e30f;
#pragma unroll
            for (int t = 0; t < 8; ++t) {
                mx0 = fmaxf(mx0, fmaxf(S[t][0], S[t][1]));
                mx1 = fmaxf(mx1, fmaxf(S[t][2], S[t][3]));
            }
            mx0 = fmaxf(mx0, __shfl_xor_sync(0xffffffffu, mx0, 1));
            mx0 = fmaxf(mx0, __shfl_xor_sync(0xffffffffu, mx0, 2));
            mx1 = fmaxf(mx1, __shfl_xor_sync(0xffffffffu, mx1, 1));
            mx1 = fmaxf(mx1, __shfl_xor_sync(0xffffffffu, mx1, 2));
            const float mn0 = fmaxf(m0, mx0), mn1 = fmaxf(m1, mx1);
            const float a0 = __expf(m0 - mn0), a1 = __expf(m1 - mn1);
            m0 = mn0; m1 = mn1;
            float s0 = 0.f, s1 = 0.f;
#pragma unroll
            for (int t = 0; t < 8; ++t) {
                S[t][0] = __expf(S[t][0] - m0); s0 += S[t][0];
                S[t][1] = __expf(S[t][1] - m0); s0 += S[t][1];
                S[t][2] = __expf(S[t][2] - m1); s1 += S[t][2];
                S[t][3] = __expf(S[t][3] - m1); s1 += S[t][3];
            }
            s0 += __shfl_xor_sync(0xffffffffu, s0, 1);
            s0 += __shfl_xor_sync(0xffffffffu, s0, 2);
            s1 += __shfl_xor_sync(0xffffffffu, s1, 1);
            s1 += __shfl_xor_sync(0xffffffffu, s1, 2);
            l0 = l0 * a0 + s0;
            l1 = l1 * a1 + s1;
#pragma unroll
            for (int t = 0; t < 16; ++t) {
                O[t][0] *= a0; O[t][1] *= a0; O[t][2] *= a1; O[t][3] *= a1;
            }

            // ---- repack P (C-frag -> A-frag), hi/lo split ----
            uint32_t ph[4][4], pl[4][4];
#pragma unroll
            for (int kc = 0; kc < 4; ++kc) {
                ph[kc][0] = packbf2(S[2 * kc][0],     S[2 * kc][1]);
                ph[kc][1] = packbf2(S[2 * kc][2],     S[2 * kc][3]);
                ph[kc][2] = packbf2(S[2 * kc + 1][0], S[2 * kc + 1][1]);
                ph[kc][3] = packbf2(S[2 * kc + 1][2], S[2 * kc + 1][3]);
#pragma unroll
                for (int r = 0; r < 4; ++r) {
                    const __nv_bfloat162 hb = *(const __nv_bfloat162*)&ph[kc][r];
                    const int tt = 2 * kc + (r >> 1);
                    const int c0 = (r & 1) * 2;
                    pl[kc][r] = packbf2(S[tt][c0]     - __bfloat162float(hb.x),
                                        S[tt][c0 + 1] - __bfloat162float(hb.y));
                }
            }

            // ---- O += P V ----
            const uint32_t vbb = sb + V_OFF + buf * 32768;
#pragma unroll
            for (int dt = 0; dt < 8; ++dt) {
#pragma unroll
                for (int kc = 0; kc < 4; ++kc) {
                    const uint32_t voff = SW128((dt * 16 + nIn) * 128 + kc * 32 + kB);
                    uint32_t vh0, vh1, vh2, vh3, vl0, vl1, vl2, vl3;
                    LDSM_X4(vh0, vh1, vh2, vh3, vbb + voff);
                    LDSM_X4(vl0, vl1, vl2, vl3, vbb + 16384 + voff);
                    MMA_BF16(O[dt * 2],     ph[kc], vh0, vh1);
                    MMA_BF16(O[dt * 2],     pl[kc], vh0, vh1);
                    MMA_BF16(O[dt * 2],     ph[kc], vl0, vl1);
                    MMA_BF16(O[dt * 2 + 1], ph[kc], vh2, vh3);
                    MMA_BF16(O[dt * 2 + 1], pl[kc], vh2, vh3);
                    MMA_BF16(O[dt * 2 + 1], ph[kc], vl2, vl3);
                }
            }
        }
        __syncthreads();
    }

    // ---- epilogue: O / l -> g_ctx[b][s][h*128 + d] ----
    const int rg = q0 + wq + (lane >> 2);
    const float inv0 = 1.f / l0, inv1 = 1.f / l1;
#pragma unroll
    for (int t = 0; t < 16; ++t) {
        const int col = h * HD + t * 8 + 2 * (lane & 3);
        float* dst0 = g_ctx + ((size_t)b * S_LEN + rg) * H_DIM + col;
        float* dst1 = g_ctx + ((size_t)b * S_LEN + rg + 8) * H_DIM + col;
        *(float2*)dst0 = make_float2(O[t][0] * inv0, O[t][1] * inv0);
        *(float2*)dst1 = make_float2(O[t][2] * inv1, O[t][3] * inv1);
    }
}

// ---------------------------------------------------------------------------
// launch
// ---------------------------------------------------------------------------
extern "C" void kernel_launch(void* const* d_in, const int* in_sizes, int n_in,
                              void* d_out, int out_size)
{
    const float* x    = (const float*)d_in[0];
    const float* Wqkv = (const float*)d_in[1];
    const float* Wo   = (const float*)d_in[2];
    float* out = (float*)d_out;

    float* ctx = nullptr;  cudaGetSymbolAddress((void**)&ctx, g_ctx);
    __nv_bfloat16 *xh, *xl, *wqh, *wql, *woh, *wol, *ch, *cl;
    cudaGetSymbolAddress((void**)&xh,  g_xh);
    cudaGetSymbolAddress((void**)&xl,  g_xl);
    cudaGetSymbolAddress((void**)&wqh, g_wqkv_h);
    cudaGetSymbolAddress((void**)&wql, g_wqkv_l);
    cudaGetSymbolAddress((void**)&woh, g_wo_h);
    cudaGetSymbolAddress((void**)&wol, g_wo_l);
    cudaGetSymbolAddress((void**)&ch,  g_ch);
    cudaGetSymbolAddress((void**)&cl,  g_cl);

    static bool attr_done = false;
    if (!attr_done) {
        cudaFuncSetAttribute(gemm_bf16<0>, cudaFuncAttributeMaxDynamicSharedMemorySize, GEMM_SMEM);
        cudaFuncSetAttribute(gemm_bf16<1>, cudaFuncAttributeMaxDynamicSharedMemorySize, GEMM_SMEM);
        cudaFuncSetAttribute(flash_attn_mma, cudaFuncAttributeMaxDynamicSharedMemorySize, ATT_SMEM);
        attr_done = true;
    }

    // 0) split/transpose conversions
    {
        const int n4 = (M_ROWS * H_DIM) / 4;
        split_kernel<<<(n4 + 255) / 256, 256>>>(x, xh, xl, n4);
        transpose_split<<<dim3(N_QKV / 32, H_DIM / 32), dim3(32, 8)>>>(Wqkv, wqh, wql, H_DIM, N_QKV);
        transpose_split<<<dim3(H_DIM / 32, H_DIM / 32), dim3(32, 8)>>>(Wo, woh, wol, H_DIM, H_DIM);
    }

    // 1) QKV projection (tensor), scatter into g_q/g_k/g_v
    gemm_bf16<0><<<dim3(M_ROWS / 128, N_QKV / 128), 256, GEMM_SMEM>>>(
        xh, xl, wqh, wql, nullptr, H_DIM, N_QKV);

    // 2) RoPE + bf16 split (Q,K) ; V transpose + split
    rope_cvt<<<(B_SZ * NH * S_LEN * 64) / 256, 256>>>();
    v_cvt_t<<<dim3(S_LEN / 32, HD / 32, B_SZ * NH), dim3(32, 8)>>>();

    // 3) tensor-core flash attention
    flash_attn_mma<<<dim3(S_LEN / 128, NH, B_SZ), 256, ATT_SMEM>>>();

    // 4) split ctx, then output projection (tensor) -> d_out
    {
        const int n4 = (M_ROWS * H_DIM) / 4;
        split_kernel<<<(n4 + 255) / 256, 256>>>(ctx, ch, cl, n4);
    }
    gemm_bf16<1><<<dim3(M_ROWS / 128, H_DIM / 128), 256, GEMM_SMEM>>>(
        ch, cl, woh, wol, out, H_DIM, H_DIM);
}